// round 10
// baseline (speedup 1.0000x reference)
#include <cuda_runtime.h>
#include <cstdint>
#include <cstddef>

// CTC loss (faithful to reference incl. input_len = C bug).
// B=512, T=512 (row stride), C=128, Tu=128, L=64, S=129, blank=127.
// THREE warps per row with overlapping halos (dependency flows upward only,
// <=2 states/step):
//   W0: states 0..63   (lane: 2L blank / 2L+1 label L)        exact always
//   W1: states 32..95  (lane: 32+2L / 33+2L, label 16+L)      owns 64..95
//   W2: states 64..128 (lane: 64+2L / 65+2L, label 32+L)      owns 96..128
// Every 8 steps warps exchange 32 boundary states + a row-wide max via smem
// (2 syncthreads per chunk). Linear domain, row-consistent power-of-2 rescale.
// 12-warp blocks (4 rows) -> 128 blocks -> 3 warps/SMSP on 128 SMs.

#define B_    512
#define T_    512
#define C_    128
#define L_    64
#define BLANK 127
#define EPSF  (1e-7f)
#define LN2F  0.69314718055994530942f

#define ROWS   4            // rows per block
#define CHUNK  8
#define NBUF   4
#define NCHUNK 16           // 128 timesteps
#define STG_F  (ROWS * NBUF * CHUNK * C_)   // staging floats (16384 = 64 KB)
#define XB_F   (ROWS * 64)                  // 2 boundary sets x 32 states per row
#define MX_F   (ROWS * 4)                   // 3 used, padded
#define SMEM_BYTES ((STG_F + XB_F + MX_F) * 4)

__device__ __forceinline__ void cpasync16(uint32_t saddr, const void* g) {
    asm volatile("cp.async.cg.shared.global [%0], [%1], 16;" :: "r"(saddr), "l"(g));
}
__device__ __forceinline__ void cp_commit() { asm volatile("cp.async.commit_group;"); }
__device__ __forceinline__ void cp_wait2()  { asm volatile("cp.async.wait_group 2;"); }

__device__ __forceinline__ int redux_max(int v) {
    int r; asm volatile("redux.sync.max.s32 %0, %1, 0xffffffff;" : "=r"(r) : "r"(v));
    return r;
}

__global__ __launch_bounds__(ROWS * 96, 1)
void ctc_kernel(const int* __restrict__ y_true,
                const float* __restrict__ y_pred,
                float* __restrict__ out)
{
    extern __shared__ float sm[];
    float* stg = sm;                  // [ROWS][NBUF][CHUNK][C_]
    float* xb  = sm + STG_F;          // [ROWS][2][32] boundary states
    float* mx  = xb + XB_F;           // [ROWS][3] per-warp maxima (bits as float)

    const unsigned FULL = 0xffffffffu;
    const int lane = threadIdx.x & 31;
    const int w    = threadIdx.x >> 5;       // 0..11
    const int r    = w / 3;                  // row within block
    const int role = w - r * 3;              // 0,1,2
    const int b    = blockIdx.x * ROWS + r;

    float* mystg = stg + (size_t)r * NBUF * CHUNK * C_;
    const uint32_t smbase = (uint32_t)__cvta_generic_to_shared(mystg);
    const float* __restrict__ row = y_pred + (size_t)b * T_ * C_;
    const int*   __restrict__ lab = y_true + b * L_;

    // this lane's label + skip flag (odd state 2*li+1, li = role*16 + lane)
    const int li = role * 16 + lane;
    const int l  = lab[li];
    const float sk = (li > 0 && l != lab[li - 1]) ? 1.f : 0.f;

    auto issue_chunk = [&](int c) {          // role 0 only
        const float* g = row + (size_t)c * CHUNK * C_ + lane * 4;
        const uint32_t s = smbase +
            (uint32_t)(((c & (NBUF - 1)) * CHUNK * C_ + lane * 4) * 4);
        #pragma unroll
        for (int j = 0; j < CHUNK; ++j)
            cpasync16(s + j * C_ * 4, g + j * C_);
    };

    // ---- state: aA = even (blank) state, aB = odd (label) state -------------
    float aA = (role == 0 && lane == 0) ? 1.f : 0.f;   // virtual init
    float aB = 0.f;
    float a4 = 0.f;                                    // state 128 (W2 lane31)
    int etot = 0;

    // ---- staging prologue (role 0 warps) -------------------------------------
    if (role == 0) {
        #pragma unroll
        for (int k = 0; k < 3; ++k) { issue_chunk(k); cp_commit(); }
    }

    for (int c = 0; c < NCHUNK; ++c) {
        if (role == 0) {
            if (c + 3 < NCHUNK) issue_chunk(c + 3);
            cp_commit();
            cp_wait2();
        }
        __syncthreads();    // chunk c staged & visible; prev exchange reads done

        const float* srow = mystg + (size_t)(c & (NBUF - 1)) * CHUNK * C_;

        #pragma unroll
        for (int j = 0; j < CHUNK; ++j) {
            const float qB = srow[j * C_ + BLANK] + EPSF;
            const float qL = srow[j * C_ + l]     + EPSF;

            const float t  = __shfl_up_sync(FULL, aB, 1);  // neighbor odd state
            const float n1 = (lane == 0) ? 0.f : t;        // = sA-1 and sB-2

            const float naA = (aA + n1) * qB;              // blank state
            const float naB = fmaf(sk, n1, aB + aA) * qL;  // label state
            if (role == 2)                                  // warp-uniform branch
                a4 = (a4 + aB) * qB;                       // state 128 (lane31)
            aA = naA; aB = naB;
        }

        // local warp max (alpha >= 0 -> float bits monotonic as s32)
        {
            float mv = fmaxf(aA, aB);
            if (role == 2) mv = fmaxf(mv, (lane == 31) ? a4 : 0.f);
            const int rb = redux_max(__float_as_int(mv));
            if (lane == 0) mx[r * 4 + role] = __int_as_float(rb);
        }
        // boundary export: W0 lanes16-31 -> xb[r][0], W1 lanes16-31 -> xb[r][1]
        if (role < 2 && lane >= 16) {
            float* dst = xb + r * 64 + role * 32 + 2 * (lane - 16);
            dst[0] = aA;
            dst[1] = aB;
        }
        __syncthreads();

        // halo import: W1/W2 lanes 0-15 take producer's states (same scale domain)
        if (role > 0 && lane < 16) {
            const float* src = xb + r * 64 + (role - 1) * 32 + 2 * lane;
            aA = src[0];
            aB = src[1];
        }
        // row-wide power-of-two rescale (identical e in all 3 warps)
        {
            const float m0 = mx[r * 4 + 0];
            const float m1 = mx[r * 4 + 1];
            const float m2 = mx[r * 4 + 2];
            const float rm = fmaxf(fmaxf(m0, m1), m2);
            const int   e  = (__float_as_int(rm) >> 23) - 127;
            const float sc = __int_as_float((127 - e) << 23);  // 2^-e
            aA *= sc; aB *= sc;
            if (role == 2) a4 *= sc;
            etot += e;
        }
    }

    // ---- loss = -( ln(alpha[127] + alpha[128]) + etot*ln2 ) ------------------
    if (role == 2 && lane == 31) {
        const float s = aB + a4;      // states 127 (aB) and 128 (a4)
        out[b] = -(__logf(s) + (float)etot * LN2F);
    }
}

extern "C" void kernel_launch(void* const* d_in, const int* in_sizes, int n_in,
                              void* d_out, int out_size)
{
    const int* y_true;
    const float* y_pred;
    if (n_in >= 2 && in_sizes[0] == B_ * L_) {
        y_true = (const int*)d_in[0];
        y_pred = (const float*)d_in[1];
    } else {
        y_true = (const int*)d_in[1];
        y_pred = (const float*)d_in[0];
    }
    float* out = (float*)d_out;

    cudaFuncSetAttribute(ctc_kernel,
                         cudaFuncAttributeMaxDynamicSharedMemorySize, SMEM_BYTES);

    // 128 blocks x 384 threads (4 rows x 3 warps) -> 3 warps/SMSP on 128 SMs
    ctc_kernel<<<B_ / ROWS, ROWS * 96, SMEM_BYTES>>>(y_true, y_pred, out);
}